// round 1
// baseline (speedup 1.0000x reference)
#include <cuda_runtime.h>
#include <math.h>

#define BSZ 2048
#define TT 8
#define NQ 10
#define SDIM 1024
#define NT 256

// Scratch (no allocation allowed): h, c carry state across timesteps; gate pre-activations.
__device__ float g_h[BSZ * NQ];
__device__ float g_c[BSZ * NQ];
__device__ float g_gates[6 * BSZ * NQ];

struct C2 { float x, y; };
__device__ __forceinline__ C2 cmul(C2 a, C2 b) {
    return { a.x * b.x - a.y * b.y, a.x * b.y + a.y * b.x };
}

// Column offsets / counts of the 81-wide preactivation p per circuit.
// c0 forget: p[0:10], c1 input: p[10:30], c2 output: p[30:40] (shortcut, unused),
// c3 candidate: p[40:70], c4 memory: p[70:80], c5 temporal: p[80].

__global__ __launch_bounds__(NT) void circuits_kernel(
    const float* __restrict__ x, const float* __restrict__ Wx,
    const float* __restrict__ Wh, const float* __restrict__ bias,
    const float* __restrict__ R, int t)
{
    const int b = blockIdx.x;
    const int c = blockIdx.y;
    const int tid = threadIdx.x;

    // circ_output: features are exactly [0,1,0] per qubit (RX column sums equal ->
    // uniform state x global phase; CNOT chain leaves uniform invariant).
    if (c == 2) {
        if (tid < NQ) {
            float acc = 0.f;
            #pragma unroll
            for (int q = 0; q < NQ; q++) acc += R[2 * 300 + (3 * q + 1) * 10 + tid];
            g_gates[(2 * BSZ + b) * NQ + tid] = acc;
        }
        return;
    }

    __shared__ float2 amps[SDIM];
    __shared__ float par[30];
    __shared__ C2 vsh[NQ][2];
    __shared__ float wred[NQ][3][NT / 32];
    __shared__ float feats[30];

    // ---- stage 1: compute needed columns of p = x_t @ Wx + h @ Wh + bias ----
    int off, np;
    switch (c) {
        case 0: off = 0;  np = 10; break;
        case 1: off = 10; np = 20; break;
        case 3: off = 40; np = 30; break;
        case 4: off = 70; np = 10; break;
        default: off = 80; np = 1;  break;  // c == 5
    }
    if (tid < np) {
        int j = off + tid;
        float acc = bias[j];
        const float* xb = x + (b * TT + t) * NQ;
        #pragma unroll
        for (int k = 0; k < NQ; k++) acc += xb[k] * Wx[k * 81 + j];
        if (t > 0) {
            const float* hb = g_h + b * NQ;
            #pragma unroll
            for (int k = 0; k < NQ; k++) acc += hb[k] * Wh[k * 81 + j];
        }
        par[tid] = acc;
    }
    __syncthreads();

    // ---- stage 2: per-qubit 2-vectors of the (product) pre-entangler state ----
    if (tid < NQ) {
        const float RS = 0.70710678118654752f;
        C2 v0, v1;
        if (c == 0 || c == 4) {                 // RY applied to (|0>+|1>)/sqrt2
            float th = par[tid];
            float cc = cosf(0.5f * th), ss = sinf(0.5f * th);
            v0 = { (cc - ss) * RS, 0.f };
            v1 = { (cc + ss) * RS, 0.f };
        } else if (c == 1) {                    // RZ(t2) * RY(t1) on uniform
            float t1 = par[2 * tid], t2 = par[2 * tid + 1];
            float cc = cosf(0.5f * t1), ss = sinf(0.5f * t1);
            float a0 = (cc - ss) * RS, a1 = (cc + ss) * RS;
            float ce = cosf(0.5f * t2), se = sinf(0.5f * t2);
            v0 = { a0 * ce, -a0 * se };         // * e^{-i t2/2}
            v1 = { a1 * ce,  a1 * se };         // * e^{+i t2/2}
        } else if (c == 3) {                    // RZ(p2) RY(p1) RZ(p0) H |uniform> = col0 of RZ RY RZ
            float p0 = par[3 * tid], p1 = par[3 * tid + 1], p2 = par[3 * tid + 2];
            float c1 = cosf(0.5f * p1), s1 = sinf(0.5f * p1);
            float am = -0.5f * (p0 + p2);
            float ap =  0.5f * (p2 - p0);
            v0 = { c1 * cosf(am), c1 * sinf(am) };
            v1 = { s1 * cosf(ap), s1 * sinf(ap) };
        } else {                                // c == 5 temporal: U = RX(0.05t) * RZ(0.1t)
            float tp = par[0];
            float a = 0.1f * tp, bb = 0.05f * tp;
            float cb = cosf(0.5f * bb), sb = sinf(0.5f * bb);
            float ca = cosf(0.5f * a),  sa = sinf(0.5f * a);
            C2 em = { ca, -sa };                // e^{-ia/2}
            C2 ep = { ca,  sa };                // e^{+ia/2}
            C2 u00 = { cb * em.x, cb * em.y };
            C2 u01 = { sb * ep.y, -sb * ep.x }; // -i*sb*ep
            C2 u10 = { sb * em.y, -sb * em.x }; // -i*sb*em
            C2 u11 = { cb * ep.x, cb * ep.y };
            if (tid == 0) {                     // qubit 0 is in |0>: v = U (1,0)^T
                v0 = u00; v1 = u10;
            } else {                            // others uniform: v = U (1,1)^T / sqrt2
                v0 = { (u00.x + u01.x) * RS, (u00.y + u01.y) * RS };
                v1 = { (u10.x + u11.x) * RS, (u10.y + u11.y) * RS };
            }
        }
        vsh[tid][0] = v0; vsh[tid][1] = v1;
    }
    __syncthreads();

    // ---- stage 3: build full state in one pass (product x diagonal x permutation) ----
    C2 lv[NQ][2];
    #pragma unroll
    for (int q = 0; q < NQ; q++) { lv[q][0] = vsh[q][0]; lv[q][1] = vsh[q][1]; }

    float zz2 = (c == 5) ? 0.1f * par[0] : 0.f;   // theta/2 of the ZZ sandwich

    #pragma unroll
    for (int r = 0; r < SDIM / NT; r++) {
        int idx = tid + r * NT;
        int src = idx;
        if (c == 1) src = idx ^ ((idx >> 1) & 0x1FF);  // CNOT chain 0->1->...->9 composed

        C2 a = lv[0][(src >> 9) & 1];
        #pragma unroll
        for (int q = 1; q < NQ; q++) a = cmul(a, lv[q][(src >> (9 - q)) & 1]);

        if (c == 0) {
            // T on all qubits (phase pi/4 * popcount) + CZ pairs (0,1)(2,3)(4,5)(6,7)(8,9)
            int pc = __popc(idx);
            int sgn = __popc(idx & (idx >> 1) & 0x155) & 1;
            float ang = 0.78539816339744831f * (float)pc;
            float sn, cs;
            sincosf(ang, &sn, &cs);
            if (sgn) { cs = -cs; sn = -sn; }
            a = cmul(a, C2{ cs, sn });
        } else if (c == 4) {
            if (__popc(idx & (idx >> 1) & 0x155) & 1) { a.x = -a.x; a.y = -a.y; }
        } else if (c == 3) {
            const int CM[14] = { 0x280,0x202,0x201,0x140,0x108,0x0C0,0x0A0,
                                 0x090,0x088,0x084,0x081,0x044,0x028,0x011 };
            int p14 = 0;
            #pragma unroll
            for (int m = 0; m < 14; m++) p14 ^= ((idx & CM[m]) == CM[m]);
            if (p14) { a.x = -a.x; a.y = -a.y; }
        } else if (c == 5) {
            int d = __popc((idx ^ (idx >> 1)) & 0x1FF);
            float A = zz2 * (float)(2 * d - 9);
            float sn, cs;
            sincosf(A, &sn, &cs);
            a = cmul(a, C2{ cs, sn });
        }
        amps[idx] = make_float2(a.x, a.y);
    }
    __syncthreads();

    // ---- stage 4: measure 30 features (10 qubits x [p0-p1, 2Re, 2Im]) ----
    const int wid = tid >> 5, lane = tid & 31;
    #pragma unroll
    for (int q = 0; q < NQ; q++) {
        int bp = 9 - q;
        float dd = 0.f, rr = 0.f, ii = 0.f;
        #pragma unroll
        for (int r = 0; r < (SDIM / 2) / NT; r++) {
            int p = tid + r * NT;
            int i0 = ((p >> bp) << (bp + 1)) | (p & ((1 << bp) - 1));
            int i1 = i0 | (1 << bp);
            float2 a0 = amps[i0];
            float2 a1 = amps[i1];
            dd += a0.x * a0.x + a0.y * a0.y - a1.x * a1.x - a1.y * a1.y;
            rr += a0.x * a1.x + a0.y * a1.y;
            ii += a0.x * a1.y - a0.y * a1.x;
        }
        #pragma unroll
        for (int o = 16; o > 0; o >>= 1) {
            dd += __shfl_down_sync(0xffffffffu, dd, o);
            rr += __shfl_down_sync(0xffffffffu, rr, o);
            ii += __shfl_down_sync(0xffffffffu, ii, o);
        }
        if (lane == 0) {
            wred[q][0][wid] = dd;
            wred[q][1][wid] = rr;
            wred[q][2][wid] = ii;
        }
    }
    __syncthreads();

    if (tid < 30) {
        int q = tid / 3, k = tid % 3;
        float s = 0.f;
        #pragma unroll
        for (int w = 0; w < NT / 32; w++) s += wred[q][k][w];
        feats[tid] = (k == 0) ? s : 2.f * s;
    }
    __syncthreads();

    // ---- stage 5: feats @ R[c] -> gate preactivations ----
    if (tid < NQ) {
        const float* Rc = R + c * 300;
        float acc = 0.f;
        #pragma unroll
        for (int f = 0; f < 30; f++) acc += feats[f] * Rc[f * 10 + tid];
        g_gates[(c * BSZ + b) * NQ + tid] = acc;
    }
}

__global__ void update_kernel(float* __restrict__ out, int t)
{
    int i = blockIdx.x * blockDim.x + threadIdx.x;
    if (i >= BSZ * NQ) return;
    int b = i / NQ, n = i % NQ;
    float G[6];
    #pragma unroll
    for (int c = 0; c < 6; c++) G[c] = g_gates[(c * BSZ + b) * NQ + n];
    float fg = 1.f / (1.f + expf(-G[0]));
    float ig = 1.f / (1.f + expf(-G[1]));
    float og = 1.f / (1.f + expf(-G[2]));
    float gg = tanhf(G[3]);
    float mq = 1.f / (1.f + expf(-G[4]));
    float tm = tanhf(G[5]);
    float cold = (t == 0) ? 0.f : g_c[i];
    float cn = (fg * cold + ig * gg) * mq;
    float hn = og * tanhf(cn) + 0.1f * tm;
    g_c[i] = cn;
    g_h[i] = hn;
    out[(b * TT + t) * NQ + n] = hn;
}

extern "C" void kernel_launch(void* const* d_in, const int* in_sizes, int n_in,
                              void* d_out, int out_size)
{
    const float* x    = (const float*)d_in[0];
    const float* Wx   = (const float*)d_in[1];
    const float* Wh   = (const float*)d_in[2];
    const float* bias = (const float*)d_in[3];
    const float* R    = (const float*)d_in[4];
    float* out = (float*)d_out;

    dim3 grid(BSZ, 6);
    for (int t = 0; t < TT; t++) {
        circuits_kernel<<<grid, NT>>>(x, Wx, Wh, bias, R, t);
        update_kernel<<<(BSZ * NQ + 255) / 256, 256>>>(out, t);
    }
}

// round 2
// speedup vs baseline: 14.9461x; 14.9461x over previous
#include <cuda_runtime.h>
#include <math.h>

#define BSZ 2048
#define TT 8
#define NQ 10
#define WPB 8
#define NBLK (BSZ / WPB)

__global__ __launch_bounds__(256) void qlstm_kernel(
    const float* __restrict__ x, const float* __restrict__ Wx,
    const float* __restrict__ Wh, const float* __restrict__ bias,
    const float* __restrict__ R, float* __restrict__ out)
{
    __shared__ float sWx[810], sWh[810], sBias[81], sR[1800], sG2[NQ];
    __shared__ float sP[WPB][84];
    __shared__ float sPz[WPB][5][NQ], sXr[WPB][5][NQ], sXi[WPB][5][NQ];
    __shared__ float sF[WPB][5][30];
    __shared__ float sG[WPB][5][NQ];
    __shared__ float sH[WPB][NQ], sXin[WPB][NQ];
    __shared__ float sPP[WPB][NQ + 2];

    const int tid = threadIdx.x, w = tid >> 5, lane = tid & 31;
    const int b = blockIdx.x * WPB + w;

    for (int i = tid; i < 810; i += 256) { sWx[i] = Wx[i]; sWh[i] = Wh[i]; }
    for (int i = tid; i < 1800; i += 256) sR[i] = R[i];
    if (tid < 81) sBias[tid] = bias[tid];
    __syncthreads();
    if (tid < NQ) {
        // circ_output state is exactly uniform x phase -> feats = [0,1,0] per qubit
        float acc = 0.f;
        #pragma unroll
        for (int q = 0; q < NQ; q++) acc += sR[600 + (3*q+1)*10 + tid];
        sG2[tid] = acc;
    }
    if (lane < NQ) sH[w][lane] = 0.f;
    __syncthreads();

    float creg = 0.f;

    for (int t = 0; t < TT; t++) {
        if (lane < NQ) sXin[w][lane] = x[(b*TT + t)*NQ + lane];
        __syncwarp();

        // ---- p = x_t @ Wx + h @ Wh + bias (81 cols over 32 lanes) ----
        for (int j = lane; j < 81; j += 32) {
            float acc = sBias[j];
            #pragma unroll
            for (int k = 0; k < NQ; k++)
                acc = fmaf(sXin[w][k], sWx[k*81+j], fmaf(sH[w][k], sWh[k*81+j], acc));
            sP[w][j] = acc;
        }
        __syncwarp();

        // ---- per (circuit,qubit): Pz = |v0|^2-|v1|^2, X = conj(v0)*v1 ----
        // slots s: 0->forget, 1->input, 2->candidate, 3->memory, 4->temporal
        for (int tk = lane; tk < 50; tk += 32) {
            int s = tk / 10, q = tk - s*10;
            float pz, xr, xi;
            if (s == 0 || s == 3) {                 // RY on uniform
                float th = sP[w][(s==0 ? 0 : 70) + q], sn, cs;
                sincosf(th, &sn, &cs);
                pz = -sn; xr = 0.5f*cs; xi = 0.f;
            } else if (s == 1) {                    // RZ*RY on uniform
                float t1 = sP[w][10+2*q], t2 = sP[w][11+2*q];
                float s1, c1; sincosf(t1, &s1, &c1);
                float s2, c2v; sincosf(t2, &s2, &c2v);
                pz = -s1; xr = 0.5f*c1*c2v; xi = 0.5f*c1*s2;
            } else if (s == 2) {                    // RZ RY RZ H |0>
                float p1 = sP[w][41+3*q], p2 = sP[w][42+3*q];
                float s1, c1; sincosf(p1, &s1, &c1);
                float s2, c2v; sincosf(p2, &s2, &c2v);
                pz = c1; xr = 0.5f*s1*c2v; xi = 0.5f*s1*s2;
            } else {                                // temporal RX(0.05t)*RZ(0.1t)
                float tp = sP[w][80];
                float a = 0.1f*tp, bb = 0.05f*tp;
                float SB, CB; sincosf(0.5f*bb, &SB, &CB);
                if (q == 0) {                       // qubit 0 input |0>
                    pz = CB*CB - SB*SB; xr = 0.f; xi = -CB*SB;
                } else {                            // input |+>
                    float SA, CA; sincosf(0.5f*a, &SA, &CA);
                    const float RS = 0.70710678118654752f;
                    float v0r = (CB*CA + SB*SA)*RS, v0i = -(CB*SA + SB*CA)*RS;
                    float v1r = (CB*CA - SB*SA)*RS, v1i = (CB*SA - SB*CA)*RS;
                    pz = v0r*v0r + v0i*v0i - v1r*v1r - v1i*v1i;
                    xr = v0r*v1r + v0i*v1i;
                    xi = v0r*v1i - v0i*v1r;
                }
            }
            sPz[w][s][q] = pz; sXr[w][s][q] = xr; sXi[w][s][q] = xi;
        }
        __syncwarp();

        // prefix products of Pz for the CNOT-chain circuit (input)
        if (lane == 0) {
            float pp = 1.f;
            sPP[w][0] = 1.f;
            #pragma unroll
            for (int q = 0; q < NQ; q++) { pp *= sPz[w][1][q]; sPP[w][q+1] = pp; }
        }
        __syncwarp();

        // ---- analytic features: [p0-p1, 2Re cr, 2Im cr] per qubit ----
        for (int tk = lane; tk < 50; tk += 32) {
            int s = tk / 10, q = tk - s*10;
            float f0, f1, f2;
            float pz = sPz[w][s][q], xr = sXr[w][s][q], xi = sXi[w][s][q];
            if (s == 0) {                          // T-phase e^{i pi/4} + CZ pairs
                f0 = pz;
                float tt = 1.41421356237f * xr * sPz[w][0][q^1];
                f1 = tt; f2 = tt;
            } else if (s == 1) {                   // CNOT chain
                f0 = sPP[w][q+1];
                float C = (q <= 8) ? 2.f*sXr[w][1][q+1] : 1.f;
                f1 = 2.f*C*xr;
                f2 = 2.f*C*xi*sPP[w][q];
            } else if (s == 2) {                   // CAND_CZ partner products
                const int MASK[10] = {0x304,0x48,0x2F9,0x86,0x44,0x204,0x16,0xC,0x1,0x25};
                float prod = 1.f;
                int m = MASK[q];
                #pragma unroll
                for (int j = 0; j < NQ; j++) if ((m>>j)&1) prod *= sPz[w][2][j];
                f0 = pz; f1 = 2.f*xr*prod; f2 = 2.f*xi*prod;
            } else if (s == 3) {                   // CZ pairs, real amps
                f0 = pz; f1 = 2.f*xr*sPz[w][3][q^1]; f2 = 0.f;
            } else {                               // ZZ sandwich phases
                float z2 = 0.2f * sP[w][80];
                float s2z, c2z; sincosf(z2, &s2z, &c2z);
                float er = 1.f, ei = 0.f;
                if (q > 0)  { er = c2z; ei = s2z * sPz[w][4][q-1]; }
                if (q < 9) {
                    float fr = c2z, fi = s2z * sPz[w][4][q+1];
                    float nr = er*fr - ei*fi, ni = er*fi + ei*fr;
                    er = nr; ei = ni;
                }
                f0 = pz;
                f1 = 2.f*(xr*er - xi*ei);
                f2 = 2.f*(xr*ei + xi*er);
            }
            sF[w][s][3*q]   = f0;
            sF[w][s][3*q+1] = f1;
            sF[w][s][3*q+2] = f2;
        }
        __syncwarp();

        // ---- gates = feats @ R[c] (50 outputs over 32 lanes) ----
        {
            const int CMAP[5] = {0,1,3,4,5};
            for (int o = lane; o < 50; o += 32) {
                int s = o / 10, n = o - s*10;
                const float* Rc = sR + CMAP[s]*300 + n;
                float acc = 0.f;
                #pragma unroll
                for (int f = 0; f < 30; f++) acc = fmaf(sF[w][s][f], Rc[f*10], acc);
                sG[w][s][n] = acc;
            }
        }
        __syncwarp();

        // ---- LSTM cell update (lanes 0..9 own hidden dims) ----
        if (lane < NQ) {
            float G0 = sG[w][0][lane], G1 = sG[w][1][lane], G3 = sG[w][2][lane];
            float G4 = sG[w][3][lane], G5 = sG[w][4][lane], G2c = sG2[lane];
            float fg = 1.f/(1.f+expf(-G0));
            float ig = 1.f/(1.f+expf(-G1));
            float og = 1.f/(1.f+expf(-G2c));
            float gg = tanhf(G3);
            float mq = 1.f/(1.f+expf(-G4));
            float tm = tanhf(G5);
            float cn = (fg*creg + ig*gg)*mq;
            float hn = og*tanhf(cn) + 0.1f*tm;
            creg = cn;
            sH[w][lane] = hn;
            out[(b*TT + t)*NQ + lane] = hn;
        }
        __syncwarp();
    }
}

extern "C" void kernel_launch(void* const* d_in, const int* in_sizes, int n_in,
                              void* d_out, int out_size)
{
    const float* x    = (const float*)d_in[0];
    const float* Wx   = (const float*)d_in[1];
    const float* Wh   = (const float*)d_in[2];
    const float* bias = (const float*)d_in[3];
    const float* R    = (const float*)d_in[4];
    float* out = (float*)d_out;

    qlstm_kernel<<<NBLK, 256>>>(x, Wx, Wh, bias, R, out);
}

// round 3
// speedup vs baseline: 30.6645x; 2.0517x over previous
#include <cuda_runtime.h>
#include <math.h>

#define BSZ 2048
#define TT 8
#define NQ 10
#define WPB 4
#define NBLK (BSZ / WPB)

__device__ __forceinline__ float fast_tanh(float x) {
    float y;
    asm("tanh.approx.f32 %0, %1;" : "=f"(y) : "f"(x));
    return y;
}
__device__ __forceinline__ float fast_sigmoid(float x) {
    return 0.5f * fast_tanh(0.5f * x) + 0.5f;
}

__global__ __launch_bounds__(32 * WPB) void qlstm_kernel(
    const float* __restrict__ x, const float* __restrict__ Wx,
    const float* __restrict__ Wh, const float* __restrict__ bias,
    const float* __restrict__ R, float* __restrict__ out)
{
    __shared__ float sWx[810], sWh[810], sBias[81], sR[1800], sG2[NQ];
    __shared__ float sP[WPB][84];
    __shared__ float sPz[WPB][5][NQ], sXr[WPB][5][NQ], sXi[WPB][5][NQ];
    __shared__ float sF[WPB][5][30];
    __shared__ float sG[WPB][5][NQ];
    __shared__ float sH[WPB][NQ], sXin[WPB][NQ];
    __shared__ float sPP[WPB][NQ + 2];

    const int tid = threadIdx.x, w = tid >> 5, lane = tid & 31;
    const int b = blockIdx.x * WPB + w;
    const int NTH = 32 * WPB;

    for (int i = tid; i < 810; i += NTH) { sWx[i] = Wx[i]; sWh[i] = Wh[i]; }
    for (int i = tid; i < 1800; i += NTH) sR[i] = R[i];
    if (tid < 81) sBias[tid] = bias[tid];
    __syncthreads();
    if (tid < NQ) {
        // circ_output state is uniform x phase -> feats = [0,1,0] per qubit
        float acc = 0.f;
        #pragma unroll
        for (int q = 0; q < NQ; q++) acc += sR[600 + (3*q+1)*10 + tid];
        sG2[tid] = acc;
    }
    if (lane < NQ) sH[w][lane] = 0.f;
    __syncthreads();

    float creg = 0.f;

    for (int t = 0; t < TT; t++) {
        if (lane < NQ) sXin[w][lane] = x[(b*TT + t)*NQ + lane];
        __syncwarp();

        // ---- p = x_t @ Wx + h @ Wh + bias (81 cols over 32 lanes) ----
        for (int j = lane; j < 81; j += 32) {
            float acc = sBias[j];
            #pragma unroll
            for (int k = 0; k < NQ; k++)
                acc = fmaf(sXin[w][k], sWx[k*81+j], fmaf(sH[w][k], sWh[k*81+j], acc));
            sP[w][j] = acc;
        }
        __syncwarp();

        // ---- per (circuit,qubit): Pz = |v0|^2-|v1|^2, X = conj(v0)*v1 ----
        // slots s: 0->forget, 1->input, 2->candidate, 3->memory, 4->temporal
        for (int tk = lane; tk < 50; tk += 32) {
            int s = tk / 10, q = tk - s*10;
            float pz, xr, xi;
            if (s == 0 || s == 3) {                 // RY on uniform
                float th = sP[w][(s==0 ? 0 : 70) + q], sn, cs;
                __sincosf(th, &sn, &cs);
                pz = -sn; xr = 0.5f*cs; xi = 0.f;
            } else if (s == 1) {                    // RZ*RY on uniform
                float t1 = sP[w][10+2*q], t2 = sP[w][11+2*q];
                float s1, c1; __sincosf(t1, &s1, &c1);
                float s2, c2v; __sincosf(t2, &s2, &c2v);
                pz = -s1; xr = 0.5f*c1*c2v; xi = 0.5f*c1*s2;
            } else if (s == 2) {                    // RZ RY RZ H |0>
                float p1 = sP[w][41+3*q], p2 = sP[w][42+3*q];
                float s1, c1; __sincosf(p1, &s1, &c1);
                float s2, c2v; __sincosf(p2, &s2, &c2v);
                pz = c1; xr = 0.5f*s1*c2v; xi = 0.5f*s1*s2;
            } else {                                // temporal RX(0.05t)*RZ(0.1t)
                float tp = sP[w][80];
                float a = 0.1f*tp, bb = 0.05f*tp;
                float SB, CB; __sincosf(0.5f*bb, &SB, &CB);
                if (q == 0) {                       // qubit 0 input |0>
                    pz = CB*CB - SB*SB; xr = 0.f; xi = -CB*SB;
                } else {                            // input |+>
                    float SA, CA; __sincosf(0.5f*a, &SA, &CA);
                    const float RS = 0.70710678118654752f;
                    float v0r = (CB*CA + SB*SA)*RS, v0i = -(CB*SA + SB*CA)*RS;
                    float v1r = (CB*CA - SB*SA)*RS, v1i = (CB*SA - SB*CA)*RS;
                    pz = v0r*v0r + v0i*v0i - v1r*v1r - v1i*v1i;
                    xr = v0r*v1r + v0i*v1i;
                    xi = v0r*v1i - v0i*v1r;
                }
            }
            sPz[w][s][q] = pz; sXr[w][s][q] = xr; sXi[w][s][q] = xi;
        }
        __syncwarp();

        // prefix products of Pz for the CNOT-chain circuit (input)
        if (lane == 0) {
            float pp = 1.f;
            sPP[w][0] = 1.f;
            #pragma unroll
            for (int q = 0; q < NQ; q++) { pp *= sPz[w][1][q]; sPP[w][q+1] = pp; }
        }
        __syncwarp();

        // ---- analytic features: [p0-p1, 2Re cr, 2Im cr] per qubit ----
        for (int tk = lane; tk < 50; tk += 32) {
            int s = tk / 10, q = tk - s*10;
            float f0, f1, f2;
            float pz = sPz[w][s][q], xr = sXr[w][s][q], xi = sXi[w][s][q];
            if (s == 0) {                          // T-phase e^{i pi/4} + CZ pairs
                f0 = pz;
                float tt = 1.41421356237f * xr * sPz[w][0][q^1];
                f1 = tt; f2 = tt;
            } else if (s == 1) {                   // CNOT chain
                f0 = sPP[w][q+1];
                float C = (q <= 8) ? 2.f*sXr[w][1][q+1] : 1.f;
                f1 = 2.f*C*xr;
                f2 = 2.f*C*xi*sPP[w][q];
            } else if (s == 2) {                   // CAND_CZ partner products
                const int MASK[10] = {0x304,0x48,0x2F9,0x86,0x44,0x204,0x16,0xC,0x1,0x25};
                float prod = 1.f;
                int m = MASK[q];
                #pragma unroll
                for (int j = 0; j < NQ; j++) if ((m>>j)&1) prod *= sPz[w][2][j];
                f0 = pz; f1 = 2.f*xr*prod; f2 = 2.f*xi*prod;
            } else if (s == 3) {                   // CZ pairs, real amps
                f0 = pz; f1 = 2.f*xr*sPz[w][3][q^1]; f2 = 0.f;
            } else {                               // ZZ sandwich phases
                float z2 = 0.2f * sP[w][80];
                float s2z, c2z; __sincosf(z2, &s2z, &c2z);
                float er = 1.f, ei = 0.f;
                if (q > 0)  { er = c2z; ei = s2z * sPz[w][4][q-1]; }
                if (q < 9) {
                    float fr = c2z, fi = s2z * sPz[w][4][q+1];
                    float nr = er*fr - ei*fi, ni = er*fi + ei*fr;
                    er = nr; ei = ni;
                }
                f0 = pz;
                f1 = 2.f*(xr*er - xi*ei);
                f2 = 2.f*(xr*ei + xi*er);
            }
            sF[w][s][3*q]   = f0;
            sF[w][s][3*q+1] = f1;
            sF[w][s][3*q+2] = f2;
        }
        __syncwarp();

        // ---- gates = feats @ R[c] (50 outputs over 32 lanes) ----
        {
            const int CMAP[5] = {0,1,3,4,5};
            for (int o = lane; o < 50; o += 32) {
                int s = o / 10, n = o - s*10;
                const float* Rc = sR + CMAP[s]*300 + n;
                float acc = 0.f;
                #pragma unroll
                for (int f = 0; f < 30; f++) acc = fmaf(sF[w][s][f], Rc[f*10], acc);
                sG[w][s][n] = acc;
            }
        }
        __syncwarp();

        // ---- LSTM cell update (lanes 0..9 own hidden dims) ----
        if (lane < NQ) {
            float G0 = sG[w][0][lane], G1 = sG[w][1][lane], G3 = sG[w][2][lane];
            float G4 = sG[w][3][lane], G5 = sG[w][4][lane], G2c = sG2[lane];
            float fg = fast_sigmoid(G0);
            float ig = fast_sigmoid(G1);
            float og = fast_sigmoid(G2c);
            float gg = fast_tanh(G3);
            float mq = fast_sigmoid(G4);
            float tm = fast_tanh(G5);
            float cn = (fg*creg + ig*gg)*mq;
            float hn = og*fast_tanh(cn) + 0.1f*tm;
            creg = cn;
            sH[w][lane] = hn;
            out[(b*TT + t)*NQ + lane] = hn;
        }
        __syncwarp();
    }
}

extern "C" void kernel_launch(void* const* d_in, const int* in_sizes, int n_in,
                              void* d_out, int out_size)
{
    const float* x    = (const float*)d_in[0];
    const float* Wx   = (const float*)d_in[1];
    const float* Wh   = (const float*)d_in[2];
    const float* bias = (const float*)d_in[3];
    const float* R    = (const float*)d_in[4];
    float* out = (float*)d_out;

    qlstm_kernel<<<NBLK, 32 * WPB>>>(x, Wx, Wh, bias, R, out);
}

// round 6
// speedup vs baseline: 37.6648x; 1.2283x over previous
#include <cuda_runtime.h>
#include <math.h>

#define BSZ 2048
#define TT 8
#define NQ 10
#define WPB 4
#define NBLK (BSZ / WPB)
#define FULLM 0xffffffffu

__device__ __forceinline__ float fast_tanh(float x) {
    float y;
    asm("tanh.approx.f32 %0, %1;" : "=f"(y) : "f"(x));
    return y;
}
__device__ __forceinline__ float fast_sigmoid(float x) {
    return 0.5f * fast_tanh(0.5f * x) + 0.5f;
}

__global__ __launch_bounds__(32 * WPB, 4) void qlstm_kernel(
    const float* __restrict__ x, const float* __restrict__ Wx,
    const float* __restrict__ Wh, const float* __restrict__ bias,
    const float* __restrict__ R, float* __restrict__ out)
{
    __shared__ float sR[1800], sG2[NQ];
    __shared__ float sP[WPB][84];
    __shared__ float sPz[WPB][5][NQ], sXr[WPB][5][NQ], sXi[WPB][5][NQ];
    __shared__ float sF[WPB][5][30];
    __shared__ float sG[WPB][5][NQ];
    __shared__ float sPP[WPB][NQ + 2];

    const int tid = threadIdx.x, w = tid >> 5, lane = tid & 31;
    const int b = blockIdx.x * WPB + w;
    const int NTH = 32 * WPB;

    for (int i = tid; i < 1800; i += NTH) sR[i] = R[i];
    __syncthreads();
    if (tid < NQ) {
        // circ_output state is uniform x phase -> feats = [0,1,0] per qubit
        float acc = 0.f;
        #pragma unroll
        for (int q = 0; q < NQ; q++) acc += sR[600 + (3*q+1)*10 + tid];
        sG2[tid] = acc;
    }
    __syncthreads();

    // ---- register-resident weight columns: lane owns cols lane, lane+32, lane+64 ----
    float wx0[NQ], wh0[NQ], wx1[NQ], wh1[NQ], wx2[NQ], wh2[NQ];
    const bool has2 = (lane < 17);
    #pragma unroll
    for (int k = 0; k < NQ; k++) {
        wx0[k] = Wx[k*81 + lane];
        wh0[k] = Wh[k*81 + lane];
        wx1[k] = Wx[k*81 + lane + 32];
        wh1[k] = Wh[k*81 + lane + 32];
        wx2[k] = has2 ? Wx[k*81 + lane + 64] : 0.f;
        wh2[k] = has2 ? Wh[k*81 + lane + 64] : 0.f;
    }
    const float b0 = bias[lane], b1 = bias[lane + 32];
    const float b2 = has2 ? bias[lane + 64] : 0.f;

    float creg = 0.f;
    float hv = 0.f;                       // h for hidden dim = lane (lanes 0..9)

    for (int t = 0; t < TT; t++) {
        float xv = (lane < NQ) ? x[(b*TT + t)*NQ + lane] : 0.f;

        // ---- p = x_t @ Wx + h @ Wh + bias, fully in registers + shuffles ----
        float p0 = b0, p1 = b1, p2 = b2;
        #pragma unroll
        for (int k = 0; k < NQ; k++) {
            float xk = __shfl_sync(FULLM, xv, k);
            float hk = __shfl_sync(FULLM, hv, k);
            p0 = fmaf(xk, wx0[k], fmaf(hk, wh0[k], p0));
            p1 = fmaf(xk, wx1[k], fmaf(hk, wh1[k], p1));
            p2 = fmaf(xk, wx2[k], fmaf(hk, wh2[k], p2));
        }
        sP[w][lane] = p0;
        sP[w][lane + 32] = p1;
        if (has2) sP[w][lane + 64] = p2;
        __syncwarp();

        // ---- per (circuit,qubit): Pz = |v0|^2-|v1|^2, X = conj(v0)*v1 ----
        // slots s: 0->forget, 1->input, 2->candidate, 3->memory, 4->temporal
        for (int tk = lane; tk < 50; tk += 32) {
            int s = tk / 10, q = tk - s*10;
            float pz, xr, xi;
            if (s == 0 || s == 3) {                 // RY on uniform
                float th = sP[w][(s==0 ? 0 : 70) + q], sn, cs;
                __sincosf(th, &sn, &cs);
                pz = -sn; xr = 0.5f*cs; xi = 0.f;
            } else if (s == 1) {                    // RZ*RY on uniform
                float t1 = sP[w][10+2*q], t2 = sP[w][11+2*q];
                float s1, c1; __sincosf(t1, &s1, &c1);
                float s2, c2v; __sincosf(t2, &s2, &c2v);
                pz = -s1; xr = 0.5f*c1*c2v; xi = 0.5f*c1*s2;
            } else if (s == 2) {                    // RZ RY RZ H |0>
                float p1q = sP[w][41+3*q], p2q = sP[w][42+3*q];
                float s1, c1; __sincosf(p1q, &s1, &c1);
                float s2, c2v; __sincosf(p2q, &s2, &c2v);
                pz = c1; xr = 0.5f*s1*c2v; xi = 0.5f*s1*s2;
            } else {                                // temporal RX(0.05t)*RZ(0.1t)
                float tp = sP[w][80];
                float a = 0.1f*tp, bb = 0.05f*tp;
                float SB, CB; __sincosf(0.5f*bb, &SB, &CB);
                if (q == 0) {                       // qubit 0 input |0>
                    pz = CB*CB - SB*SB; xr = 0.f; xi = -CB*SB;
                } else {                            // input |+>
                    float SA, CA; __sincosf(0.5f*a, &SA, &CA);
                    const float RS = 0.70710678118654752f;
                    float v0r = (CB*CA + SB*SA)*RS, v0i = -(CB*SA + SB*CA)*RS;
                    float v1r = (CB*CA - SB*SA)*RS, v1i = (CB*SA - SB*CA)*RS;
                    pz = v0r*v0r + v0i*v0i - v1r*v1r - v1i*v1i;
                    xr = v0r*v1r + v0i*v1i;
                    xi = v0r*v1i - v0i*v1r;
                }
            }
            sPz[w][s][q] = pz; sXr[w][s][q] = xr; sXi[w][s][q] = xi;
        }
        __syncwarp();

        // prefix products of Pz for the CNOT-chain circuit (input)
        if (lane == 0) {
            float pp = 1.f;
            sPP[w][0] = 1.f;
            #pragma unroll
            for (int q = 0; q < NQ; q++) { pp *= sPz[w][1][q]; sPP[w][q+1] = pp; }
        }
        __syncwarp();

        // ---- analytic features: [p0-p1, 2Re cr, 2Im cr] per qubit ----
        for (int tk = lane; tk < 50; tk += 32) {
            int s = tk / 10, q = tk - s*10;
            float f0, f1, f2;
            float pz = sPz[w][s][q], xr = sXr[w][s][q], xi = sXi[w][s][q];
            if (s == 0) {                          // T-phase e^{i pi/4} + CZ pairs
                f0 = pz;
                float tt = 1.41421356237f * xr * sPz[w][0][q^1];
                f1 = tt; f2 = tt;
            } else if (s == 1) {                   // CNOT chain
                f0 = sPP[w][q+1];
                float C = (q <= 8) ? 2.f*sXr[w][1][q+1] : 1.f;
                f1 = 2.f*C*xr;
                f2 = 2.f*C*xi*sPP[w][q];
            } else if (s == 2) {                   // CAND_CZ partner products
                const int MASK[10] = {0x304,0x48,0x2F9,0x86,0x44,0x204,0x16,0xC,0x1,0x25};
                float prod = 1.f;
                int m = MASK[q];
                #pragma unroll
                for (int j = 0; j < NQ; j++) if ((m>>j)&1) prod *= sPz[w][2][j];
                f0 = pz; f1 = 2.f*xr*prod; f2 = 2.f*xi*prod;
            } else if (s == 3) {                   // CZ pairs, real amps
                f0 = pz; f1 = 2.f*xr*sPz[w][3][q^1]; f2 = 0.f;
            } else {                               // ZZ sandwich phases
                float z2 = 0.2f * sP[w][80];
                float s2z, c2z; __sincosf(z2, &s2z, &c2z);
                float er = 1.f, ei = 0.f;
                if (q > 0)  { er = c2z; ei = s2z * sPz[w][4][q-1]; }
                if (q < 9) {
                    float fr = c2z, fi = s2z * sPz[w][4][q+1];
                    float nr = er*fr - ei*fi, ni = er*fi + ei*fr;
                    er = nr; ei = ni;
                }
                f0 = pz;
                f1 = 2.f*(xr*er - xi*ei);
                f2 = 2.f*(xr*ei + xi*er);
            }
            sF[w][s][3*q]   = f0;
            sF[w][s][3*q+1] = f1;
            sF[w][s][3*q+2] = f2;
        }
        __syncwarp();

        // ---- gates = feats @ R[c] (50 outputs over 32 lanes) ----
        {
            const int CMAP[5] = {0,1,3,4,5};
            for (int o = lane; o < 50; o += 32) {
                int s = o / 10, n = o - s*10;
                const float* Rc = sR + CMAP[s]*300 + n;
                float acc = 0.f;
                #pragma unroll
                for (int f = 0; f < 30; f++) acc = fmaf(sF[w][s][f], Rc[f*10], acc);
                sG[w][s][n] = acc;
            }
        }
        __syncwarp();

        // ---- LSTM cell update (lanes 0..9 own hidden dims) ----
        float hn = 0.f;
        if (lane < NQ) {
            float G0 = sG[w][0][lane], G1 = sG[w][1][lane], G3 = sG[w][2][lane];
            float G4 = sG[w][3][lane], G5 = sG[w][4][lane], G2c = sG2[lane];
            float fg = fast_sigmoid(G0);
            float ig = fast_sigmoid(G1);
            float og = fast_sigmoid(G2c);
            float gg = fast_tanh(G3);
            float mq = fast_sigmoid(G4);
            float tm = fast_tanh(G5);
            float cn = (fg*creg + ig*gg)*mq;
            hn = og*fast_tanh(cn) + 0.1f*tm;
            creg = cn;
            out[(b*TT + t)*NQ + lane] = hn;
        }
        hv = hn;
        __syncwarp();
    }
}

extern "C" void kernel_launch(void* const* d_in, const int* in_sizes, int n_in,
                              void* d_out, int out_size)
{
    const float* x    = (const float*)d_in[0];
    const float* Wx   = (const float*)d_in[1];
    const float* Wh   = (const float*)d_in[2];
    const float* bias = (const float*)d_in[3];
    const float* R    = (const float*)d_in[4];
    float* out = (float*)d_out;

    qlstm_kernel<<<NBLK, 32 * WPB>>>(x, Wx, Wh, bias, R, out);
}